// round 1
// baseline (speedup 1.0000x reference)
#include <cuda_runtime.h>
#include <cstdint>

#define NN 100000
#define NE 1600000

// ---------------- scratch (device globals; no allocation allowed) ----------
__device__ float g_h1[(size_t)NN * 512];   // 204.8 MB
__device__ float g_h2[(size_t)NN * 256];   // 102.4 MB
__device__ float g_hA[(size_t)NN * 64];    // 25.6 MB
__device__ float g_hB[(size_t)NN * 64];    // 25.6 MB
__device__ float g_deg[2 * NN];            // [0..NN)=out-deg(src), [NN..2NN)=in-deg(dst)
__device__ float g_nrm[2 * NN];            // [0..NN)=norm_src, [NN..2NN)=norm_dst

// ---------------- small utility kernels ------------------------------------
__global__ void zero_kernel(float* __restrict__ p, int n) {
    int i = blockIdx.x * blockDim.x + threadIdx.x;
    if (i < n) p[i] = 0.0f;
}

__global__ void zero4_kernel(float4* __restrict__ p, int n4) {
    int i = blockIdx.x * blockDim.x + threadIdx.x;
    if (i < n4) p[i] = make_float4(0.f, 0.f, 0.f, 0.f);
}

__global__ void deg_kernel(const int* __restrict__ src, const int* __restrict__ dst,
                           float* __restrict__ deg) {
    int e = blockIdx.x * blockDim.x + threadIdx.x;
    if (e < NE) {
        atomicAdd(&deg[src[e]], 1.0f);
        atomicAdd(&deg[NN + dst[e]], 1.0f);
    }
}

__global__ void norm_kernel(const float* __restrict__ deg, float* __restrict__ nrm) {
    int i = blockIdx.x * blockDim.x + threadIdx.x;
    if (i < 2 * NN) nrm[i] = rsqrtf(fmaxf(deg[i], 1.0f));
}

// ---------------- edge scatter: agg[dst] += h[src] * norm_src[src] ---------
// 64 floats per edge = 16 float4 chunks; one thread per (edge, chunk).
__global__ void edge_scatter64(const float* __restrict__ h,
                               const int* __restrict__ src, const int* __restrict__ dst,
                               const float* __restrict__ nsrc,
                               float* __restrict__ agg) {
    int idx = blockIdx.x * blockDim.x + threadIdx.x;
    if (idx >= NE * 16) return;
    int e = idx >> 4;
    int c = idx & 15;
    int s = src[e];
    int d = dst[e];
    float ns = nsrc[s];
    float4 v = *(const float4*)(h + (size_t)s * 64 + c * 4);
    float* out = agg + (size_t)d * 64 + c * 4;
    atomicAdd(out + 0, v.x * ns);
    atomicAdd(out + 1, v.y * ns);
    atomicAdd(out + 2, v.z * ns);
    atomicAdd(out + 3, v.w * ns);
}

// ---------------- tiled GEMM: C = relu( (rs .* A) @ W + b ) ----------------
// A: [M,K] row-major, W: [K,N] row-major, bias: [N], rs: optional per-row scale.
template <int BM, int BN, int BK, int TM, int TN>
__global__ void __launch_bounds__((BM / TM) * (BN / TN))
gemm_bias_relu(const float* __restrict__ A, const float* __restrict__ W,
               const float* __restrict__ bias, const float* __restrict__ rs,
               float* __restrict__ C, int M, int N, int K) {
    constexpr int THREADS = (BM / TM) * (BN / TN);
    __shared__ __align__(16) float As[BK][BM];
    __shared__ __align__(16) float Bs[BK][BN];

    const int tid = threadIdx.x;
    const int tx = tid % (BN / TN);
    const int ty = tid / (BN / TN);
    const int rowBase = blockIdx.y * BM;
    const int colBase = blockIdx.x * BN;

    float acc[TM][TN];
#pragma unroll
    for (int i = 0; i < TM; i++)
#pragma unroll
        for (int j = 0; j < TN; j++) acc[i][j] = 0.0f;

    constexpr int A_F4 = BM * BK / 4;
    constexpr int A_PER = A_F4 / THREADS;
    constexpr int B_F4 = BK * BN / 4;
    constexpr int B_PER = (B_F4 + THREADS - 1) / THREADS;

    for (int k0 = 0; k0 < K; k0 += BK) {
        // load A tile (transposed into As[k][m]); apply optional row scale
#pragma unroll
        for (int i = 0; i < A_PER; i++) {
            int idx = tid + i * THREADS;
            int m = idx / (BK / 4);
            int kq = idx % (BK / 4);
            int gm = rowBase + m;
            float4 v = make_float4(0.f, 0.f, 0.f, 0.f);
            if (gm < M) {
                v = *(const float4*)(A + (size_t)gm * K + k0 + kq * 4);
                if (rs) {
                    float s = rs[gm];
                    v.x *= s; v.y *= s; v.z *= s; v.w *= s;
                }
            }
            As[kq * 4 + 0][m] = v.x;
            As[kq * 4 + 1][m] = v.y;
            As[kq * 4 + 2][m] = v.z;
            As[kq * 4 + 3][m] = v.w;
        }
        // load B tile
#pragma unroll
        for (int i = 0; i < B_PER; i++) {
            int idx = tid + i * THREADS;
            if (idx < B_F4) {
                int kk = idx / (BN / 4);
                int nq = idx % (BN / 4);
                int gn = colBase + nq * 4;
                float4 v = make_float4(0.f, 0.f, 0.f, 0.f);
                if (gn < N) v = *(const float4*)(W + (size_t)(k0 + kk) * N + gn);
                *(float4*)&Bs[kk][nq * 4] = v;
            }
        }
        __syncthreads();

#pragma unroll
        for (int kk = 0; kk < BK; kk++) {
            float af[TM], bf[TN];
#pragma unroll
            for (int i = 0; i < TM; i += 4)
                *(float4*)&af[i] = *(const float4*)&As[kk][ty * TM + i];
#pragma unroll
            for (int j = 0; j < TN; j += 4)
                *(float4*)&bf[j] = *(const float4*)&Bs[kk][tx * TN + j];
#pragma unroll
            for (int i = 0; i < TM; i++)
#pragma unroll
                for (int j = 0; j < TN; j++) acc[i][j] = fmaf(af[i], bf[j], acc[i][j]);
        }
        __syncthreads();
    }

#pragma unroll
    for (int i = 0; i < TM; i++) {
        int gm = rowBase + ty * TM + i;
        if (gm >= M) continue;
#pragma unroll
        for (int j = 0; j < TN; j++) {
            int gn = colBase + tx * TN + j;
            if (gn >= N) continue;
            float v = acc[i][j] + bias[gn];
            C[(size_t)gm * N + gn] = fmaxf(v, 0.0f);
        }
    }
}

// ---------------- host orchestration ---------------------------------------
extern "C" void kernel_launch(void* const* d_in, const int* in_sizes, int n_in,
                              void* d_out, int out_size) {
    const float* x   = (const float*)d_in[0];
    const int* src   = (const int*)d_in[1];
    const int* dst   = (const int*)d_in[2];
    const float* W1  = (const float*)d_in[3];
    const float* b1  = (const float*)d_in[4];
    const float* W2  = (const float*)d_in[5];
    const float* b2  = (const float*)d_in[6];
    const float* W3  = (const float*)d_in[7];
    const float* b3  = (const float*)d_in[8];
    const float* Wg1 = (const float*)d_in[9];
    const float* bg1 = (const float*)d_in[10];
    const float* Wg2 = (const float*)d_in[11];
    const float* bg2 = (const float*)d_in[12];
    const float* Wg3 = (const float*)d_in[13];
    const float* bg3 = (const float*)d_in[14];
    const float* Wg4 = (const float*)d_in[15];
    const float* bg4 = (const float*)d_in[16];
    float* out = (float*)d_out;

    float *h1, *h2, *hA, *hB, *deg, *nrm;
    cudaGetSymbolAddress((void**)&h1, g_h1);
    cudaGetSymbolAddress((void**)&h2, g_h2);
    cudaGetSymbolAddress((void**)&hA, g_hA);
    cudaGetSymbolAddress((void**)&hB, g_hB);
    cudaGetSymbolAddress((void**)&deg, g_deg);
    cudaGetSymbolAddress((void**)&nrm, g_nrm);

    const float* nsrc = nrm;
    const float* ndst = nrm + NN;

    // degrees + norms
    zero_kernel<<<(2 * NN + 255) / 256, 256>>>(deg, 2 * NN);
    deg_kernel<<<(NE + 255) / 256, 256>>>(src, dst, deg);
    norm_kernel<<<(2 * NN + 255) / 256, 256>>>(deg, nrm);

    const int M = NN;

    // MLP: h1 = relu(x@W1+b1)  [100k,512]x[512,512]
    {
        dim3 grid((512 + 127) / 128, (M + 127) / 128);
        gemm_bias_relu<128, 128, 16, 8, 8><<<grid, 256>>>(x, W1, b1, nullptr, h1, M, 512, 512);
    }
    // h2 = relu(h1@W2+b2)  -> [100k,256]
    {
        dim3 grid((256 + 127) / 128, (M + 127) / 128);
        gemm_bias_relu<128, 128, 16, 8, 8><<<grid, 256>>>(h1, W2, b2, nullptr, h2, M, 256, 512);
    }
    // h3 = relu(h2@W3+b3)  -> [100k,64] into hA
    {
        dim3 grid(1, (M + 127) / 128);
        gemm_bias_relu<128, 64, 16, 8, 4><<<grid, 256>>>(h2, W3, b3, nullptr, hA, M, 64, 256);
    }

    const int n4 = NN * 64 / 4;
    const int edgeBlocks = (NE * 16 + 255) / 256;
    dim3 gcGrid(1, (M + 127) / 128);

    // GC layer 1: hA -> hB(agg) -> hA
    zero4_kernel<<<(n4 + 255) / 256, 256>>>((float4*)hB, n4);
    edge_scatter64<<<edgeBlocks, 256>>>(hA, src, dst, nsrc, hB);
    gemm_bias_relu<128, 64, 16, 8, 4><<<gcGrid, 256>>>(hB, Wg1, bg1, ndst, hA, M, 64, 64);

    // GC layer 2
    zero4_kernel<<<(n4 + 255) / 256, 256>>>((float4*)hB, n4);
    edge_scatter64<<<edgeBlocks, 256>>>(hA, src, dst, nsrc, hB);
    gemm_bias_relu<128, 64, 16, 8, 4><<<gcGrid, 256>>>(hB, Wg2, bg2, ndst, hA, M, 64, 64);

    // GC layer 3
    zero4_kernel<<<(n4 + 255) / 256, 256>>>((float4*)hB, n4);
    edge_scatter64<<<edgeBlocks, 256>>>(hA, src, dst, nsrc, hB);
    gemm_bias_relu<128, 64, 16, 8, 4><<<gcGrid, 256>>>(hB, Wg3, bg3, ndst, hA, M, 64, 64);

    // GC layer 4 -> output [100k, 40]
    zero4_kernel<<<(n4 + 255) / 256, 256>>>((float4*)hB, n4);
    edge_scatter64<<<edgeBlocks, 256>>>(hA, src, dst, nsrc, hB);
    gemm_bias_relu<128, 64, 16, 8, 4><<<gcGrid, 256>>>(hB, Wg4, bg4, ndst, out, M, 40, 64);
}

// round 2
// speedup vs baseline: 2.4738x; 2.4738x over previous
#include <cuda_runtime.h>
#include <cstdint>

#define NN 100000
#define NE 1600000

// ---------------- scratch (device globals; no allocation allowed) ----------
__device__ float g_h1[(size_t)NN * 512];   // 204.8 MB
__device__ float g_h2[(size_t)NN * 256];   // 102.4 MB
__device__ float g_hA[(size_t)NN * 64];    // 25.6 MB
__device__ float g_hB[(size_t)NN * 64];    // 25.6 MB
__device__ float g_deg[2 * NN];
__device__ float g_nrm[2 * NN];

// ---------------- small utility kernels ------------------------------------
__global__ void zero_kernel(float* __restrict__ p, int n) {
    int i = blockIdx.x * blockDim.x + threadIdx.x;
    if (i < n) p[i] = 0.0f;
}

__global__ void zero4_kernel(float4* __restrict__ p, int n4) {
    int i = blockIdx.x * blockDim.x + threadIdx.x;
    if (i < n4) p[i] = make_float4(0.f, 0.f, 0.f, 0.f);
}

__global__ void deg_kernel(const int* __restrict__ src, const int* __restrict__ dst,
                           float* __restrict__ deg) {
    int e = blockIdx.x * blockDim.x + threadIdx.x;
    if (e < NE) {
        atomicAdd(&deg[src[e]], 1.0f);
        atomicAdd(&deg[NN + dst[e]], 1.0f);
    }
}

__global__ void norm_kernel(const float* __restrict__ deg, float* __restrict__ nrm) {
    int i = blockIdx.x * blockDim.x + threadIdx.x;
    if (i < 2 * NN) nrm[i] = rsqrtf(fmaxf(deg[i], 1.0f));
}

// ---------------- edge scatter: agg[dst] += h[src] * norm_src[src] ---------
// 64 floats per edge = 16 float4 chunks; one red.global.add.v4.f32 per chunk.
__global__ void edge_scatter64(const float* __restrict__ h,
                               const int* __restrict__ src, const int* __restrict__ dst,
                               const float* __restrict__ nsrc,
                               float* __restrict__ agg) {
    int idx = blockIdx.x * blockDim.x + threadIdx.x;
    if (idx >= NE * 16) return;
    int e = idx >> 4;
    int c = idx & 15;
    int s = src[e];
    int d = dst[e];
    float ns = nsrc[s];
    float4 v = *(const float4*)(h + (size_t)s * 64 + c * 4);
    float* out = agg + (size_t)d * 64 + c * 4;
    asm volatile("red.global.add.v4.f32 [%0], {%1, %2, %3, %4};"
                 :: "l"(__cvta_generic_to_global(out)),
                    "f"(v.x * ns), "f"(v.y * ns), "f"(v.z * ns), "f"(v.w * ns)
                 : "memory");
}

// ---------------- tf32 tensor-core GEMM: C = relu(A @ W + b) ----------------
// A: [M,K] row-major fp32, W: [K,N] row-major fp32, bias[N].
// CTA tile 128x128x32, 8 warps (2x4), warp tile 64x32, mma.m16n8k8.tf32.
__device__ __forceinline__ unsigned f32_to_tf32(float x) {
    unsigned u;
    asm("cvt.rna.tf32.f32 %0, %1;" : "=r"(u) : "f"(x));
    return u;
}

__global__ void __launch_bounds__(256)
gemm_tf32_bias_relu(const float* __restrict__ A, const float* __restrict__ W,
                    const float* __restrict__ bias, float* __restrict__ C,
                    int M, int N, int K) {
    // padded, conflict-free layouts (see analysis)
    __shared__ __align__(16) float As[128][36];   // [m][k], bank = 4m+k distinct
    __shared__ __align__(16) float Bs[32][136];   // [k][n], bank = 8k+n distinct

    const int tid = threadIdx.x;
    const int lane = tid & 31;
    const int warp = tid >> 5;
    const int wm = (warp >> 2) * 64;   // warp row offset within CTA tile
    const int wn = (warp & 3) * 32;    // warp col offset
    const int g = lane >> 2;           // groupID
    const int t = lane & 3;            // threadID in group
    const int rowBase = blockIdx.y * 128;
    const int colBase = blockIdx.x * 128;

    float acc[4][4][4];
#pragma unroll
    for (int i = 0; i < 4; i++)
#pragma unroll
        for (int j = 0; j < 4; j++)
#pragma unroll
            for (int q = 0; q < 4; q++) acc[i][j][q] = 0.0f;

    for (int k0 = 0; k0 < K; k0 += 32) {
        // load A tile: 128 rows x 32 cols = 1024 float4, 4 per thread
#pragma unroll
        for (int i = 0; i < 4; i++) {
            int idx = tid + i * 256;
            int m = idx >> 3;          // 8 float4 per row
            int kq = idx & 7;
            float4 v = make_float4(0.f, 0.f, 0.f, 0.f);
            int gm = rowBase + m;
            if (gm < M) v = *(const float4*)(A + (size_t)gm * K + k0 + kq * 4);
            As[m][kq * 4 + 0] = __uint_as_float(f32_to_tf32(v.x));
            As[m][kq * 4 + 1] = __uint_as_float(f32_to_tf32(v.y));
            As[m][kq * 4 + 2] = __uint_as_float(f32_to_tf32(v.z));
            As[m][kq * 4 + 3] = __uint_as_float(f32_to_tf32(v.w));
        }
        // load B tile: 32 rows x 128 cols = 1024 float4, 4 per thread
#pragma unroll
        for (int i = 0; i < 4; i++) {
            int idx = tid + i * 256;
            int kk = idx >> 5;         // 32 float4 per row
            int nq = idx & 31;
            int gn = colBase + nq * 4;
            float4 v = make_float4(0.f, 0.f, 0.f, 0.f);
            if (gn < N) v = *(const float4*)(W + (size_t)(k0 + kk) * N + gn);
            Bs[kk][nq * 4 + 0] = __uint_as_float(f32_to_tf32(v.x));
            Bs[kk][nq * 4 + 1] = __uint_as_float(f32_to_tf32(v.y));
            Bs[kk][nq * 4 + 2] = __uint_as_float(f32_to_tf32(v.z));
            Bs[kk][nq * 4 + 3] = __uint_as_float(f32_to_tf32(v.w));
        }
        __syncthreads();

#pragma unroll
        for (int ks = 0; ks < 4; ks++) {
            const int kb = ks * 8;
            unsigned a[4][4], b[4][2];
#pragma unroll
            for (int mt = 0; mt < 4; mt++) {
                int r = wm + mt * 16 + g;
                a[mt][0] = __float_as_uint(As[r][kb + t]);
                a[mt][1] = __float_as_uint(As[r + 8][kb + t]);
                a[mt][2] = __float_as_uint(As[r][kb + t + 4]);
                a[mt][3] = __float_as_uint(As[r + 8][kb + t + 4]);
            }
#pragma unroll
            for (int nt = 0; nt < 4; nt++) {
                int n = wn + nt * 8 + g;
                b[nt][0] = __float_as_uint(Bs[kb + t][n]);
                b[nt][1] = __float_as_uint(Bs[kb + t + 4][n]);
            }
#pragma unroll
            for (int mt = 0; mt < 4; mt++)
#pragma unroll
                for (int nt = 0; nt < 4; nt++) {
                    asm volatile(
                        "mma.sync.aligned.m16n8k8.row.col.f32.tf32.tf32.f32 "
                        "{%0,%1,%2,%3}, {%4,%5,%6,%7}, {%8,%9}, {%0,%1,%2,%3};"
                        : "+f"(acc[mt][nt][0]), "+f"(acc[mt][nt][1]),
                          "+f"(acc[mt][nt][2]), "+f"(acc[mt][nt][3])
                        : "r"(a[mt][0]), "r"(a[mt][1]), "r"(a[mt][2]), "r"(a[mt][3]),
                          "r"(b[nt][0]), "r"(b[nt][1]));
                }
        }
        __syncthreads();
    }

    // epilogue: bias + relu, float2 stores
#pragma unroll
    for (int mt = 0; mt < 4; mt++) {
#pragma unroll
        for (int nt = 0; nt < 4; nt++) {
            int r0 = rowBase + wm + mt * 16 + g;
            int c = colBase + wn + nt * 8 + 2 * t;
            if (c + 1 < N || c < N) {
                float bx = (c < N) ? bias[c] : 0.f;
                float by = (c + 1 < N) ? bias[c + 1] : 0.f;
                if (r0 < M && c + 1 < N) {
                    float2 o0 = make_float2(fmaxf(acc[mt][nt][0] + bx, 0.f),
                                            fmaxf(acc[mt][nt][1] + by, 0.f));
                    *(float2*)(C + (size_t)r0 * N + c) = o0;
                } else if (r0 < M && c < N) {
                    C[(size_t)r0 * N + c] = fmaxf(acc[mt][nt][0] + bx, 0.f);
                }
                int r1 = r0 + 8;
                if (r1 < M && c + 1 < N) {
                    float2 o1 = make_float2(fmaxf(acc[mt][nt][2] + bx, 0.f),
                                            fmaxf(acc[mt][nt][3] + by, 0.f));
                    *(float2*)(C + (size_t)r1 * N + c) = o1;
                } else if (r1 < M && c < N) {
                    C[(size_t)r1 * N + c] = fmaxf(acc[mt][nt][2] + bx, 0.f);
                }
            }
        }
    }
}

// ---------------- fp32 tiled GEMM (small layers) ----------------------------
template <int BM, int BN, int BK, int TM, int TN>
__global__ void __launch_bounds__((BM / TM) * (BN / TN))
gemm_bias_relu(const float* __restrict__ A, const float* __restrict__ W,
               const float* __restrict__ bias, const float* __restrict__ rs,
               float* __restrict__ C, int M, int N, int K) {
    constexpr int THREADS = (BM / TM) * (BN / TN);
    __shared__ __align__(16) float As[BK][BM];
    __shared__ __align__(16) float Bs[BK][BN];

    const int tid = threadIdx.x;
    const int tx = tid % (BN / TN);
    const int ty = tid / (BN / TN);
    const int rowBase = blockIdx.y * BM;
    const int colBase = blockIdx.x * BN;

    float acc[TM][TN];
#pragma unroll
    for (int i = 0; i < TM; i++)
#pragma unroll
        for (int j = 0; j < TN; j++) acc[i][j] = 0.0f;

    constexpr int A_F4 = BM * BK / 4;
    constexpr int A_PER = A_F4 / THREADS;
    constexpr int B_F4 = BK * BN / 4;
    constexpr int B_PER = (B_F4 + THREADS - 1) / THREADS;

    for (int k0 = 0; k0 < K; k0 += BK) {
#pragma unroll
        for (int i = 0; i < A_PER; i++) {
            int idx = tid + i * THREADS;
            int m = idx / (BK / 4);
            int kq = idx % (BK / 4);
            int gm = rowBase + m;
            float4 v = make_float4(0.f, 0.f, 0.f, 0.f);
            if (gm < M) {
                v = *(const float4*)(A + (size_t)gm * K + k0 + kq * 4);
                if (rs) {
                    float s = rs[gm];
                    v.x *= s; v.y *= s; v.z *= s; v.w *= s;
                }
            }
            As[kq * 4 + 0][m] = v.x;
            As[kq * 4 + 1][m] = v.y;
            As[kq * 4 + 2][m] = v.z;
            As[kq * 4 + 3][m] = v.w;
        }
#pragma unroll
        for (int i = 0; i < B_PER; i++) {
            int idx = tid + i * THREADS;
            if (idx < B_F4) {
                int kk = idx / (BN / 4);
                int nq = idx % (BN / 4);
                int gn = colBase + nq * 4;
                float4 v = make_float4(0.f, 0.f, 0.f, 0.f);
                if (gn < N) v = *(const float4*)(W + (size_t)(k0 + kk) * N + gn);
                *(float4*)&Bs[kk][nq * 4] = v;
            }
        }
        __syncthreads();

#pragma unroll
        for (int kk = 0; kk < BK; kk++) {
            float af[TM], bf[TN];
#pragma unroll
            for (int i = 0; i < TM; i += 4)
                *(float4*)&af[i] = *(const float4*)&As[kk][ty * TM + i];
#pragma unroll
            for (int j = 0; j < TN; j += 4)
                *(float4*)&bf[j] = *(const float4*)&Bs[kk][tx * TN + j];
#pragma unroll
            for (int i = 0; i < TM; i++)
#pragma unroll
                for (int j = 0; j < TN; j++) acc[i][j] = fmaf(af[i], bf[j], acc[i][j]);
        }
        __syncthreads();
    }

#pragma unroll
    for (int i = 0; i < TM; i++) {
        int gm = rowBase + ty * TM + i;
        if (gm >= M) continue;
#pragma unroll
        for (int j = 0; j < TN; j++) {
            int gn = colBase + tx * TN + j;
            if (gn >= N) continue;
            float v = acc[i][j] + bias[gn];
            C[(size_t)gm * N + gn] = fmaxf(v, 0.0f);
        }
    }
}

// ---------------- host orchestration ---------------------------------------
extern "C" void kernel_launch(void* const* d_in, const int* in_sizes, int n_in,
                              void* d_out, int out_size) {
    const float* x   = (const float*)d_in[0];
    const int* src   = (const int*)d_in[1];
    const int* dst   = (const int*)d_in[2];
    const float* W1  = (const float*)d_in[3];
    const float* b1  = (const float*)d_in[4];
    const float* W2  = (const float*)d_in[5];
    const float* b2  = (const float*)d_in[6];
    const float* W3  = (const float*)d_in[7];
    const float* b3  = (const float*)d_in[8];
    const float* Wg1 = (const float*)d_in[9];
    const float* bg1 = (const float*)d_in[10];
    const float* Wg2 = (const float*)d_in[11];
    const float* bg2 = (const float*)d_in[12];
    const float* Wg3 = (const float*)d_in[13];
    const float* bg3 = (const float*)d_in[14];
    const float* Wg4 = (const float*)d_in[15];
    const float* bg4 = (const float*)d_in[16];
    float* out = (float*)d_out;

    float *h1, *h2, *hA, *hB, *deg, *nrm;
    cudaGetSymbolAddress((void**)&h1, g_h1);
    cudaGetSymbolAddress((void**)&h2, g_h2);
    cudaGetSymbolAddress((void**)&hA, g_hA);
    cudaGetSymbolAddress((void**)&hB, g_hB);
    cudaGetSymbolAddress((void**)&deg, g_deg);
    cudaGetSymbolAddress((void**)&nrm, g_nrm);

    const float* nsrc = nrm;
    const float* ndst = nrm + NN;

    zero_kernel<<<(2 * NN + 255) / 256, 256>>>(deg, 2 * NN);
    deg_kernel<<<(NE + 255) / 256, 256>>>(src, dst, deg);
    norm_kernel<<<(2 * NN + 255) / 256, 256>>>(deg, nrm);

    const int M = NN;

    // MLP layer 1: [100k,512] @ [512,512] (tf32 tensor cores)
    {
        dim3 grid(512 / 128, (M + 127) / 128);
        gemm_tf32_bias_relu<<<grid, 256>>>(x, W1, b1, h1, M, 512, 512);
    }
    // MLP layer 2: [100k,512] @ [512,256] (tf32 tensor cores)
    {
        dim3 grid(256 / 128, (M + 127) / 128);
        gemm_tf32_bias_relu<<<grid, 256>>>(h1, W2, b2, h2, M, 256, 512);
    }
    // MLP layer 3: [100k,256] @ [256,64] (fp32)
    {
        dim3 grid(1, (M + 127) / 128);
        gemm_bias_relu<128, 64, 16, 8, 4><<<grid, 256>>>(h2, W3, b3, nullptr, hA, M, 64, 256);
    }

    const int n4 = NN * 64 / 4;
    const int edgeBlocks = (NE * 16 + 255) / 256;
    dim3 gcGrid(1, (M + 127) / 128);

    // GC layer 1
    zero4_kernel<<<(n4 + 255) / 256, 256>>>((float4*)hB, n4);
    edge_scatter64<<<edgeBlocks, 256>>>(hA, src, dst, nsrc, hB);
    gemm_bias_relu<128, 64, 16, 8, 4><<<gcGrid, 256>>>(hB, Wg1, bg1, ndst, hA, M, 64, 64);

    // GC layer 2
    zero4_kernel<<<(n4 + 255) / 256, 256>>>((float4*)hB, n4);
    edge_scatter64<<<edgeBlocks, 256>>>(hA, src, dst, nsrc, hB);
    gemm_bias_relu<128, 64, 16, 8, 4><<<gcGrid, 256>>>(hB, Wg2, bg2, ndst, hA, M, 64, 64);

    // GC layer 3
    zero4_kernel<<<(n4 + 255) / 256, 256>>>((float4*)hB, n4);
    edge_scatter64<<<edgeBlocks, 256>>>(hA, src, dst, nsrc, hB);
    gemm_bias_relu<128, 64, 16, 8, 4><<<gcGrid, 256>>>(hB, Wg3, bg3, ndst, hA, M, 64, 64);

    // GC layer 4 -> output [100k, 40]
    zero4_kernel<<<(n4 + 255) / 256, 256>>>((float4*)hB, n4);
    edge_scatter64<<<edgeBlocks, 256>>>(hA, src, dst, nsrc, hB);
    gemm_bias_relu<128, 64, 16, 8, 4><<<gcGrid, 256>>>(hB, Wg4, bg4, ndst, out, M, 40, 64);
}

// round 3
// speedup vs baseline: 3.9754x; 1.6070x over previous
#include <cuda_runtime.h>
#include <cstdint>

#define NN 100000
#define NE 1600000
#define NB_SCAN 98   // ceil(NN/1024)

// ---------------- scratch (device globals; no allocation allowed) ----------
__device__ float g_h1[(size_t)NN * 512];
__device__ float g_h2[(size_t)NN * 256];
__device__ float g_hA[(size_t)NN * 64];
__device__ float g_hB[(size_t)NN * 64];
__device__ float g_degf[NN];
__device__ float g_nrm[2 * NN];      // [0..NN)=norm_src, [NN..2NN)=norm_dst
__device__ int   g_cnt[NN];
__device__ int   g_rowptr[NN];
__device__ int   g_cursor[NN];
__device__ int   g_bsum[128];
__device__ int   g_col[NE];

// ---------------- utility kernels -------------------------------------------
__global__ void zero_f(float* __restrict__ p, int n) {
    int i = blockIdx.x * blockDim.x + threadIdx.x;
    if (i < n) p[i] = 0.0f;
}
__global__ void zero_i(int* __restrict__ p, int n) {
    int i = blockIdx.x * blockDim.x + threadIdx.x;
    if (i < n) p[i] = 0;
}
__global__ void deg_src_kernel(const int* __restrict__ src, float* __restrict__ degf) {
    int e = blockIdx.x * blockDim.x + threadIdx.x;
    if (e < NE) atomicAdd(&degf[src[e]], 1.0f);
}
__global__ void hist_dst_kernel(const int* __restrict__ dst, int* __restrict__ cnt) {
    int e = blockIdx.x * blockDim.x + threadIdx.x;
    if (e < NE) atomicAdd(&cnt[dst[e]], 1);
}
__global__ void norm_kernel(const float* __restrict__ degf, const int* __restrict__ cnt,
                            float* __restrict__ nrm) {
    int i = blockIdx.x * blockDim.x + threadIdx.x;
    if (i < NN) {
        nrm[i] = rsqrtf(fmaxf(degf[i], 1.0f));
        nrm[NN + i] = rsqrtf(fmaxf((float)cnt[i], 1.0f));
    }
}

// ---------------- CSR build: scan of in-degree histogram ---------------------
__global__ void scan1(const int* __restrict__ cnt, int* __restrict__ excl,
                      int* __restrict__ bsum) {
    __shared__ int sh[1024];
    int tid = threadIdx.x;
    int i = blockIdx.x * 1024 + tid;
    int v = (i < NN) ? cnt[i] : 0;
    sh[tid] = v;
    __syncthreads();
    for (int off = 1; off < 1024; off <<= 1) {
        int t = (tid >= off) ? sh[tid - off] : 0;
        __syncthreads();
        sh[tid] += t;
        __syncthreads();
    }
    if (i < NN) excl[i] = sh[tid] - v;
    if (tid == 1023) bsum[blockIdx.x] = sh[1023];
}
__global__ void scan2(int* __restrict__ bsum) {
    __shared__ int sh[128];
    int tid = threadIdx.x;
    int v = (tid < NB_SCAN) ? bsum[tid] : 0;
    sh[tid] = v;
    __syncthreads();
    for (int off = 1; off < 128; off <<= 1) {
        int t = (tid >= off) ? sh[tid - off] : 0;
        __syncthreads();
        sh[tid] += t;
        __syncthreads();
    }
    if (tid < NB_SCAN) bsum[tid] = sh[tid] - v;
}
__global__ void scan3(int* __restrict__ excl, const int* __restrict__ bsum,
                      int* __restrict__ cursor) {
    int i = blockIdx.x * 1024 + threadIdx.x;
    if (i < NN) {
        int r = excl[i] + bsum[blockIdx.x];
        excl[i] = r;
        cursor[i] = r;
    }
}
__global__ void fill_csr(const int* __restrict__ src, const int* __restrict__ dst,
                         int* __restrict__ cursor, int* __restrict__ col) {
    int e = blockIdx.x * blockDim.x + threadIdx.x;
    if (e < NE) {
        int p = atomicAdd(&cursor[dst[e]], 1);
        col[p] = src[e];
    }
}

// ---------------- CSR gather: agg[d] = sum_{e in in(d)} h[src[e]] ------------
// h rows are pre-scaled by norm_src at the producing GEMM's epilogue.
// 16 consecutive lanes per node; each lane owns a float4 chunk (256B/row).
__global__ void gather_csr(const float* __restrict__ h, const int* __restrict__ rowptr,
                           const int* __restrict__ col, float* __restrict__ agg) {
    int t = threadIdx.x;
    int node = blockIdx.x * 16 + (t >> 4);
    if (node >= NN) return;
    int c = t & 15;
    int beg = rowptr[node];
    int end = (node == NN - 1) ? NE : rowptr[node + 1];
    float4 acc = make_float4(0.f, 0.f, 0.f, 0.f);
    for (int i = beg; i < end; i++) {
        int s = __ldg(&col[i]);
        float4 v = *(const float4*)(h + (size_t)s * 64 + c * 4);
        acc.x += v.x; acc.y += v.y; acc.z += v.z; acc.w += v.w;
    }
    *(float4*)(agg + (size_t)node * 64 + c * 4) = acc;
}

// ---------------- tf32 tensor-core GEMM, cp.async 3-stage pipeline -----------
// C[r,:] = ws[r] * relu( rs[r] * (A@W)[r,:] + b )   (rs/ws optional)
// A:[M,K] row fp32, W:[K,N] row fp32. BM=128, BK=32, 8 warps, BN in {128,64}.
__device__ __forceinline__ void cp_async16(uint32_t saddr, const void* gaddr, int sz) {
    asm volatile("cp.async.cg.shared.global [%0], [%1], 16, %2;\n"
                 :: "r"(saddr), "l"(gaddr), "r"(sz));
}

template <int BN>
__global__ void __launch_bounds__(256, 2)
gemm_tf32(const float* __restrict__ A, const float* __restrict__ W,
          const float* __restrict__ bias, const float* __restrict__ rs,
          const float* __restrict__ ws, float* __restrict__ C,
          int M, int N, int K) {
    constexpr int STAGES = 3;
    constexpr int AS_STRIDE = 36;
    constexpr int BS_STRIDE = BN + 8;
    constexpr int A_ELE = 128 * AS_STRIDE;
    constexpr int B_ELE = 32 * BS_STRIDE;
    constexpr int WN_WARPS = BN / 32;          // 4 or 2
    constexpr int WM_WARPS = 8 / WN_WARPS;     // 2 or 4
    constexpr int MT = 8 / WM_WARPS;           // 4 or 2 (x 16 rows)
    constexpr int NQ = BN / 4;                 // float4 per B row
    constexpr int B_PER = (32 * NQ) / 256;     // 4 or 2

    extern __shared__ float smem[];
    float* AsBase = smem;
    float* BsBase = smem + STAGES * A_ELE;
    uint32_t smem_u32 = (uint32_t)__cvta_generic_to_shared(smem);
    uint32_t As_u32 = smem_u32;
    uint32_t Bs_u32 = smem_u32 + STAGES * A_ELE * 4;

    const int tid = threadIdx.x;
    const int lane = tid & 31;
    const int warp = tid >> 5;
    const int wm = (warp / WN_WARPS) * (MT * 16);
    const int wn = (warp % WN_WARPS) * 32;
    const int g = lane >> 2;
    const int tq = lane & 3;
    const int rowBase = blockIdx.y * 128;
    const int colBase = blockIdx.x * BN;
    const int KT = K / 32;

    float acc[MT][4][4];
#pragma unroll
    for (int i = 0; i < MT; i++)
#pragma unroll
        for (int j = 0; j < 4; j++)
#pragma unroll
            for (int q = 0; q < 4; q++) acc[i][j][q] = 0.0f;

    // per-thread load coords
    const int a_m = tid >> 3;          // + 32*i
    const int a_kq = tid & 7;

    auto issue = [&](int stage, int kt) {
        const int k0 = kt * 32;
#pragma unroll
        for (int i = 0; i < 4; i++) {
            int m = a_m + i * 32;
            const float* gsrc = A + (size_t)(rowBase + m) * K + k0 + a_kq * 4;
            uint32_t sdst = As_u32 + (stage * A_ELE + m * AS_STRIDE + a_kq * 4) * 4;
            cp_async16(sdst, gsrc, (rowBase + m < M) ? 16 : 0);
        }
#pragma unroll
        for (int i = 0; i < B_PER; i++) {
            int idx = tid + i * 256;
            int kk = idx / NQ;
            int nq = idx % NQ;
            int gn = colBase + nq * 4;
            const float* gsrc = W + (size_t)(k0 + kk) * N + gn;
            uint32_t sdst = Bs_u32 + (stage * B_ELE + kk * BS_STRIDE + nq * 4) * 4;
            cp_async16(sdst, gsrc, (gn + 3 < N) ? 16 : 0);
        }
    };

    // prologue: stages 0,1
#pragma unroll
    for (int p = 0; p < 2; p++) {
        if (p < KT) issue(p, p);
        asm volatile("cp.async.commit_group;\n" ::: "memory");
    }

    for (int kt = 0; kt < KT; kt++) {
        if (kt + 2 < KT) issue((kt + 2) % STAGES, kt + 2);
        asm volatile("cp.async.commit_group;\n" ::: "memory");
        asm volatile("cp.async.wait_group 2;\n" ::: "memory");
        __syncthreads();

        const float* As = AsBase + (kt % STAGES) * A_ELE;
        const float* Bs = BsBase + (kt % STAGES) * B_ELE;
#pragma unroll
        for (int ks = 0; ks < 4; ks++) {
            const int kb = ks * 8;
            unsigned a[MT][4], b[4][2];
#pragma unroll
            for (int mt = 0; mt < MT; mt++) {
                int r = wm + mt * 16 + g;
                a[mt][0] = __float_as_uint(As[r * AS_STRIDE + kb + tq]);
                a[mt][1] = __float_as_uint(As[(r + 8) * AS_STRIDE + kb + tq]);
                a[mt][2] = __float_as_uint(As[r * AS_STRIDE + kb + tq + 4]);
                a[mt][3] = __float_as_uint(As[(r + 8) * AS_STRIDE + kb + tq + 4]);
            }
#pragma unroll
            for (int nt = 0; nt < 4; nt++) {
                int n = wn + nt * 8 + g;
                b[nt][0] = __float_as_uint(Bs[(kb + tq) * BS_STRIDE + n]);
                b[nt][1] = __float_as_uint(Bs[(kb + tq + 4) * BS_STRIDE + n]);
            }
#pragma unroll
            for (int mt = 0; mt < MT; mt++)
#pragma unroll
                for (int nt = 0; nt < 4; nt++) {
                    asm volatile(
                        "mma.sync.aligned.m16n8k8.row.col.f32.tf32.tf32.f32 "
                        "{%0,%1,%2,%3}, {%4,%5,%6,%7}, {%8,%9}, {%0,%1,%2,%3};"
                        : "+f"(acc[mt][nt][0]), "+f"(acc[mt][nt][1]),
                          "+f"(acc[mt][nt][2]), "+f"(acc[mt][nt][3])
                        : "r"(a[mt][0]), "r"(a[mt][1]), "r"(a[mt][2]), "r"(a[mt][3]),
                          "r"(b[nt][0]), "r"(b[nt][1]));
                }
        }
        __syncthreads();
    }

    // epilogue: rs (pre-bias row scale), bias, relu, ws (post-relu row scale)
#pragma unroll
    for (int mt = 0; mt < MT; mt++) {
        int r0 = rowBase + wm + mt * 16 + g;
        int r1 = r0 + 8;
        float rs0 = 1.f, rs1 = 1.f, ws0 = 1.f, ws1 = 1.f;
        if (rs) {
            if (r0 < M) rs0 = rs[r0];
            if (r1 < M) rs1 = rs[r1];
        }
        if (ws) {
            if (r0 < M) ws0 = ws[r0];
            if (r1 < M) ws1 = ws[r1];
        }
#pragma unroll
        for (int nt = 0; nt < 4; nt++) {
            int c = colBase + wn + nt * 8 + 2 * tq;
            float bx = (c < N) ? bias[c] : 0.f;
            float by = (c + 1 < N) ? bias[c + 1] : 0.f;
            if (r0 < M) {
                float vx = ws0 * fmaxf(acc[mt][nt][0] * rs0 + bx, 0.f);
                float vy = ws0 * fmaxf(acc[mt][nt][1] * rs0 + by, 0.f);
                if (c + 1 < N) *(float2*)(C + (size_t)r0 * N + c) = make_float2(vx, vy);
                else if (c < N) C[(size_t)r0 * N + c] = vx;
            }
            if (r1 < M) {
                float vx = ws1 * fmaxf(acc[mt][nt][2] * rs1 + bx, 0.f);
                float vy = ws1 * fmaxf(acc[mt][nt][3] * rs1 + by, 0.f);
                if (c + 1 < N) *(float2*)(C + (size_t)r1 * N + c) = make_float2(vx, vy);
                else if (c < N) C[(size_t)r1 * N + c] = vx;
            }
        }
    }
}

// ---------------- host orchestration ---------------------------------------
extern "C" void kernel_launch(void* const* d_in, const int* in_sizes, int n_in,
                              void* d_out, int out_size) {
    const float* x   = (const float*)d_in[0];
    const int* src   = (const int*)d_in[1];
    const int* dst   = (const int*)d_in[2];
    const float* W1  = (const float*)d_in[3];
    const float* b1  = (const float*)d_in[4];
    const float* W2  = (const float*)d_in[5];
    const float* b2  = (const float*)d_in[6];
    const float* W3  = (const float*)d_in[7];
    const float* b3  = (const float*)d_in[8];
    const float* Wg1 = (const float*)d_in[9];
    const float* bg1 = (const float*)d_in[10];
    const float* Wg2 = (const float*)d_in[11];
    const float* bg2 = (const float*)d_in[12];
    const float* Wg3 = (const float*)d_in[13];
    const float* bg3 = (const float*)d_in[14];
    const float* Wg4 = (const float*)d_in[15];
    const float* bg4 = (const float*)d_in[16];
    float* out = (float*)d_out;

    float *h1, *h2, *hA, *hB, *degf, *nrm;
    int *cnt, *rowptr, *cursor, *bsum, *col;
    cudaGetSymbolAddress((void**)&h1, g_h1);
    cudaGetSymbolAddress((void**)&h2, g_h2);
    cudaGetSymbolAddress((void**)&hA, g_hA);
    cudaGetSymbolAddress((void**)&hB, g_hB);
    cudaGetSymbolAddress((void**)&degf, g_degf);
    cudaGetSymbolAddress((void**)&nrm, g_nrm);
    cudaGetSymbolAddress((void**)&cnt, g_cnt);
    cudaGetSymbolAddress((void**)&rowptr, g_rowptr);
    cudaGetSymbolAddress((void**)&cursor, g_cursor);
    cudaGetSymbolAddress((void**)&bsum, g_bsum);
    cudaGetSymbolAddress((void**)&col, g_col);

    const float* nsrc = nrm;
    const float* ndst = nrm + NN;

    // opt-in to large dynamic smem (idempotent host-side calls)
    constexpr int SMEM128 = 3 * (128 * 36 + 32 * 136) * 4;
    constexpr int SMEM64  = 3 * (128 * 36 + 32 * 72) * 4;
    cudaFuncSetAttribute(gemm_tf32<128>, cudaFuncAttributeMaxDynamicSharedMemorySize, SMEM128);
    cudaFuncSetAttribute(gemm_tf32<64>,  cudaFuncAttributeMaxDynamicSharedMemorySize, SMEM64);

    // degrees + norms + CSR
    zero_f<<<(NN + 255) / 256, 256>>>(degf, NN);
    zero_i<<<(NN + 255) / 256, 256>>>(cnt, NN);
    deg_src_kernel<<<(NE + 255) / 256, 256>>>(src, degf);
    hist_dst_kernel<<<(NE + 255) / 256, 256>>>(dst, cnt);
    norm_kernel<<<(NN + 255) / 256, 256>>>(degf, cnt, nrm);
    scan1<<<NB_SCAN, 1024>>>(cnt, rowptr, bsum);
    scan2<<<1, 128>>>(bsum);
    scan3<<<NB_SCAN, 1024>>>(rowptr, bsum, cursor);
    fill_csr<<<(NE + 255) / 256, 256>>>(src, dst, cursor, col);

    const int M = NN;
    dim3 gA(4, (M + 127) / 128);   // N=512
    dim3 gB(2, (M + 127) / 128);   // N=256
    dim3 gS(1, (M + 127) / 128);   // N<=64

    // MLP
    gemm_tf32<128><<<gA, 256, SMEM128>>>(x,  W1, b1, nullptr, nullptr, h1, M, 512, 512);
    gemm_tf32<128><<<gB, 256, SMEM128>>>(h1, W2, b2, nullptr, nullptr, h2, M, 256, 512);
    // layer 3 output pre-scaled by norm_src (consumed only by gather)
    gemm_tf32<64><<<gS, 256, SMEM64>>>(h2, W3, b3, nullptr, nsrc, hA, M, 64, 256);

    const int gatherBlocks = (NN + 15) / 16;

    // GC 1..3: gather -> gemm (rs=norm_dst on input, ws=norm_src on output)
    gather_csr<<<gatherBlocks, 256>>>(hA, rowptr, col, hB);
    gemm_tf32<64><<<gS, 256, SMEM64>>>(hB, Wg1, bg1, ndst, nsrc, hA, M, 64, 64);

    gather_csr<<<gatherBlocks, 256>>>(hA, rowptr, col, hB);
    gemm_tf32<64><<<gS, 256, SMEM64>>>(hB, Wg2, bg2, ndst, nsrc, hA, M, 64, 64);

    gather_csr<<<gatherBlocks, 256>>>(hA, rowptr, col, hB);
    gemm_tf32<64><<<gS, 256, SMEM64>>>(hB, Wg3, bg3, ndst, nsrc, hA, M, 64, 64);

    // GC 4 -> output [100k, 40] (no output scale)
    gather_csr<<<gatherBlocks, 256>>>(hA, rowptr, col, hB);
    gemm_tf32<64><<<gS, 256, SMEM64>>>(hB, Wg4, bg4, ndst, nullptr, out, M, 40, 64);
}

// round 5
// speedup vs baseline: 5.3637x; 1.3492x over previous
#include <cuda_runtime.h>
#include <cuda_fp16.h>
#include <cstdint>

#define NN 100000
#define NE 1600000
#define NB_SCAN 98   // ceil(NN/1024)

// ---------------- scratch (device globals; no allocation allowed) ----------
__device__ float g_h1[(size_t)NN * 512];   // holds h1 as fp16 (aliased)
__device__ float g_h2[(size_t)NN * 256];   // holds xh (fp16) first, then h2 fp32
__device__ float g_hA[(size_t)NN * 64];
__device__ float g_hB[(size_t)NN * 64];
__device__ float g_degf[NN];
__device__ float g_nrm[2 * NN];      // [0..NN)=norm_src, [NN..2NN)=norm_dst
__device__ int   g_cnt[NN];
__device__ int   g_rowptr[NN];
__device__ int   g_cursor[NN];
__device__ int   g_bsum[128];
__device__ int   g_col[NE];
// transposed fp16 weights: Wt[n][k] = W[k][n]
__device__ __half g_w1t[512 * 512];
__device__ __half g_w2t[256 * 512];

// ---------------- utility kernels -------------------------------------------
__global__ void zero_f(float* __restrict__ p, int n) {
    int i = blockIdx.x * blockDim.x + threadIdx.x;
    if (i < n) p[i] = 0.0f;
}
__global__ void zero_i(int* __restrict__ p, int n) {
    int i = blockIdx.x * blockDim.x + threadIdx.x;
    if (i < n) p[i] = 0;
}
__global__ void deg_src_kernel(const int* __restrict__ src, float* __restrict__ degf) {
    int e = blockIdx.x * blockDim.x + threadIdx.x;
    if (e < NE) atomicAdd(&degf[src[e]], 1.0f);
}
__global__ void hist_dst_kernel(const int* __restrict__ dst, int* __restrict__ cnt) {
    int e = blockIdx.x * blockDim.x + threadIdx.x;
    if (e < NE) atomicAdd(&cnt[dst[e]], 1);
}
__global__ void norm_kernel(const float* __restrict__ degf, const int* __restrict__ cnt,
                            float* __restrict__ nrm) {
    int i = blockIdx.x * blockDim.x + threadIdx.x;
    if (i < NN) {
        nrm[i] = rsqrtf(fmaxf(degf[i], 1.0f));
        nrm[NN + i] = rsqrtf(fmaxf((float)cnt[i], 1.0f));
    }
}

__device__ __forceinline__ uint32_t packh2(float lo, float hi) {
    uint32_t r;
    asm("cvt.rn.f16x2.f32 %0, %1, %2;" : "=r"(r) : "f"(hi), "f"(lo));
    return r;
}

// fp32 -> fp16 bulk convert (4 elems/thread)
__global__ void cvt_f2h(const float* __restrict__ in, __half* __restrict__ out, int n4) {
    int i = blockIdx.x * blockDim.x + threadIdx.x;
    if (i < n4) {
        float4 v = ((const float4*)in)[i];
        uint2 o;
        o.x = packh2(v.x, v.y);
        o.y = packh2(v.z, v.w);
        ((uint2*)out)[i] = o;
    }
}

// W [K,N] fp32 -> Wt [N,K] fp16 (transpose + convert)
__global__ void wcvt_kernel(const float* __restrict__ W, __half* __restrict__ Wt,
                            int K, int N) {
    int i = blockIdx.x * blockDim.x + threadIdx.x;
    if (i < K * N) {
        int n = i / K, k = i % K;
        Wt[i] = __float2half(W[(size_t)k * N + n]);
    }
}

// ---------------- CSR build --------------------------------------------------
__global__ void scan1(const int* __restrict__ cnt, int* __restrict__ excl,
                      int* __restrict__ bsum) {
    __shared__ int sh[1024];
    int tid = threadIdx.x;
    int i = blockIdx.x * 1024 + tid;
    int v = (i < NN) ? cnt[i] : 0;
    sh[tid] = v;
    __syncthreads();
    for (int off = 1; off < 1024; off <<= 1) {
        int t = (tid >= off) ? sh[tid - off] : 0;
        __syncthreads();
        sh[tid] += t;
        __syncthreads();
    }
    if (i < NN) excl[i] = sh[tid] - v;
    if (tid == 1023) bsum[blockIdx.x] = sh[1023];
}
__global__ void scan2(int* __restrict__ bsum) {
    __shared__ int sh[128];
    int tid = threadIdx.x;
    int v = (tid < NB_SCAN) ? bsum[tid] : 0;
    sh[tid] = v;
    __syncthreads();
    for (int off = 1; off < 128; off <<= 1) {
        int t = (tid >= off) ? sh[tid - off] : 0;
        __syncthreads();
        sh[tid] += t;
        __syncthreads();
    }
    if (tid < NB_SCAN) bsum[tid] = sh[tid] - v;
}
__global__ void scan3(int* __restrict__ excl, const int* __restrict__ bsum,
                      int* __restrict__ cursor) {
    int i = blockIdx.x * 1024 + threadIdx.x;
    if (i < NN) {
        int r = excl[i] + bsum[blockIdx.x];
        excl[i] = r;
        cursor[i] = r;
    }
}
__global__ void fill_csr(const int* __restrict__ src, const int* __restrict__ dst,
                         int* __restrict__ cursor, int* __restrict__ col) {
    int e = blockIdx.x * blockDim.x + threadIdx.x;
    if (e < NE) {
        int p = atomicAdd(&cursor[dst[e]], 1);
        col[p] = src[e];
    }
}

// ---------------- CSR gather -------------------------------------------------
__global__ void gather_csr(const float* __restrict__ h, const int* __restrict__ rowptr,
                           const int* __restrict__ col, float* __restrict__ agg) {
    int t = threadIdx.x;
    int node = blockIdx.x * 16 + (t >> 4);
    if (node >= NN) return;
    int c = t & 15;
    int beg = rowptr[node];
    int end = (node == NN - 1) ? NE : rowptr[node + 1];
    float4 acc = make_float4(0.f, 0.f, 0.f, 0.f);
    for (int i = beg; i < end; i++) {
        int s = __ldg(&col[i]);
        float4 v = *(const float4*)(h + (size_t)s * 64 + c * 4);
        acc.x += v.x; acc.y += v.y; acc.z += v.z; acc.w += v.w;
    }
    *(float4*)(agg + (size_t)node * 64 + c * 4) = acc;
}

// ---------------- common async copy helper ----------------------------------
__device__ __forceinline__ void cp_async16(uint32_t saddr, const void* gaddr, int sz) {
    asm volatile("cp.async.cg.shared.global [%0], [%1], 16, %2;\n"
                 :: "r"(saddr), "l"(gaddr), "r"(sz));
}

// ============================================================================
// fp16 tensor-core GEMM: C = relu(A @ Wt^T + b)
// A: [M,K] fp16 row-major, Wt: [N,K] fp16 row-major (i.e. W transposed).
// CTA tile 128x128x32, 8 warps (2x4), mma.m16n8k16, ldmatrix fragments,
// cp.async 3-stage pipeline, one __syncthreads per K-tile.
// ============================================================================
template <bool OUT_HALF>
__global__ void __launch_bounds__(256, 2)
gemm_f16(const __half* __restrict__ A, const __half* __restrict__ Wt,
         const float* __restrict__ bias, void* __restrict__ Cout,
         int M, int N, int K) {
    constexpr int STRIDE_H = 40;                  // halves per smem row (80B)
    constexpr int A_BYTES = 128 * STRIDE_H * 2;   // 10240
    constexpr int STAGE_BYTES = 2 * A_BYTES;      // A + B
    extern __shared__ char dsm[];
    uint32_t smem_u = (uint32_t)__cvta_generic_to_shared(dsm);

    const int tid = threadIdx.x;
    const int lane = tid & 31;
    const int warp = tid >> 5;
    const int wm = (warp >> 2) * 64;
    const int wn = (warp & 3) * 32;
    const int rowBase = blockIdx.y * 128;
    const int colBase = blockIdx.x * 128;
    const int KT = K / 32;

    const int lrow = lane & 7;
    const int sub = lane >> 3;            // 0..3 (A x4 tile select)
    const int subB = sub & 1;             // B x2 tile select

    float acc[4][4][4];
#pragma unroll
    for (int i = 0; i < 4; i++)
#pragma unroll
        for (int j = 0; j < 4; j++)
#pragma unroll
            for (int q = 0; q < 4; q++) acc[i][j][q] = 0.0f;

    // loader: per thread 2 A-chunks + 2 B-chunks of 16B
    const int l_m = tid >> 2;       // +64*i
    const int l_c = tid & 3;
    auto issue = [&](int stage, int kt) {
        const int k0 = kt * 32;
        uint32_t base = smem_u + stage * STAGE_BYTES;
#pragma unroll
        for (int i = 0; i < 2; i++) {
            int m = l_m + i * 64;
            const __half* gsrc = A + (size_t)(rowBase + m) * K + k0 + l_c * 8;
            cp_async16(base + m * 80 + l_c * 16, gsrc, (rowBase + m < M) ? 16 : 0);
        }
#pragma unroll
        for (int i = 0; i < 2; i++) {
            int n = l_m + i * 64;
            const __half* gsrc = Wt + (size_t)(colBase + n) * K + k0 + l_c * 8;
            cp_async16(base + A_BYTES + n * 80 + l_c * 16, gsrc, 16);
        }
    };

#pragma unroll
    for (int p = 0; p < 2; p++) {
        issue(p, p);
        asm volatile("cp.async.commit_group;\n" ::: "memory");
    }

    for (int kt = 0; kt < KT; kt++) {
        asm volatile("cp.async.wait_group 1;\n" ::: "memory");
        __syncthreads();
        const int stage = kt % 3;
        uint32_t As_u = smem_u + stage * STAGE_BYTES;
        uint32_t Bs_u = As_u + A_BYTES;

#pragma unroll
        for (int ks = 0; ks < 2; ks++) {
            const int kb = ks * 16;
            uint32_t a[4][4], b[4][2];
#pragma unroll
            for (int mt = 0; mt < 4; mt++) {
                int r = wm + mt * 16 + (sub & 1) * 8 + lrow;
                uint32_t addr = As_u + (r * STRIDE_H + kb + (sub >> 1) * 8) * 2;
                asm volatile(
                    "ldmatrix.sync.aligned.m8n8.x4.shared.b16 {%0,%1,%2,%3}, [%4];"
                    : "=r"(a[mt][0]), "=r"(a[mt][1]), "=r"(a[mt][2]), "=r"(a[mt][3])
                    : "r"(addr));
            }
#pragma unroll
            for (int nt = 0; nt < 4; nt++) {
                int n = wn + nt * 8 + lrow;
                uint32_t addr = Bs_u + (n * STRIDE_H + kb + subB * 8) * 2;
                asm volatile(
                    "ldmatrix.sync.aligned.m8n8.x2.shared.b16 {%0,%1}, [%2];"
                    : "=r"(b[nt][0]), "=r"(b[nt][1]) : "r"(addr));
            }
#pragma unroll
            for (int mt = 0; mt < 4; mt++)
#pragma unroll
                for (int nt = 0; nt < 4; nt++) {
                    asm volatile(
                        "mma.sync.aligned.m16n8k16.row.col.f32.f16.f16.f32 "
                        "{%0,%1,%2,%3}, {%4,%5,%6,%7}, {%8,%9}, {%0,%1,%2,%3};"
                        : "+f"(acc[mt][nt][0]), "+f"(acc[mt][nt][1]),
                          "+f"(acc[mt][nt][2]), "+f"(acc[mt][nt][3])
                        : "r"(a[mt][0]), "r"(a[mt][1]), "r"(a[mt][2]), "r"(a[mt][3]),
                          "r"(b[nt][0]), "r"(b[nt][1]));
                }
        }
        if (kt + 2 < KT) issue((kt + 2) % 3, kt + 2);
        asm volatile("cp.async.commit_group;\n" ::: "memory");
    }

    // epilogue: bias + relu (N is a multiple of 128 here, only row guards)
    const int g = lane >> 2;
    const int tq = lane & 3;
#pragma unroll
    for (int mt = 0; mt < 4; mt++) {
        int r0 = rowBase + wm + mt * 16 + g;
        int r1 = r0 + 8;
#pragma unroll
        for (int nt = 0; nt < 4; nt++) {
            int c = colBase + wn + nt * 8 + 2 * tq;
            float bx = __ldg(&bias[c]);
            float by = __ldg(&bias[c + 1]);
            if (r0 < M) {
                float vx = fmaxf(acc[mt][nt][0] + bx, 0.f);
                float vy = fmaxf(acc[mt][nt][1] + by, 0.f);
                if (OUT_HALF)
                    *(uint32_t*)((__half*)Cout + (size_t)r0 * N + c) = packh2(vx, vy);
                else
                    *(float2*)((float*)Cout + (size_t)r0 * N + c) = make_float2(vx, vy);
            }
            if (r1 < M) {
                float vx = fmaxf(acc[mt][nt][2] + bx, 0.f);
                float vy = fmaxf(acc[mt][nt][3] + by, 0.f);
                if (OUT_HALF)
                    *(uint32_t*)((__half*)Cout + (size_t)r1 * N + c) = packh2(vx, vy);
                else
                    *(float2*)((float*)Cout + (size_t)r1 * N + c) = make_float2(vx, vy);
            }
        }
    }
}

// ---------------- tf32 mma.sync GEMM (small layers), cp.async pipeline ------
template <int BN>
__global__ void __launch_bounds__(256, 2)
gemm_tf32(const float* __restrict__ A, const float* __restrict__ W,
          const float* __restrict__ bias, const float* __restrict__ rs,
          const float* __restrict__ ws, float* __restrict__ C,
          int M, int N, int K) {
    constexpr int STAGES = 3;
    constexpr int AS_STRIDE = 36;
    constexpr int BS_STRIDE = BN + 8;
    constexpr int A_ELE = 128 * AS_STRIDE;
    constexpr int B_ELE = 32 * BS_STRIDE;
    constexpr int WN_WARPS = BN / 32;
    constexpr int WM_WARPS = 8 / WN_WARPS;
    constexpr int MT = 8 / WM_WARPS;
    constexpr int NQ = BN / 4;
    constexpr int B_PER = (32 * NQ) / 256;

    extern __shared__ float smem[];
    float* AsBase = smem;
    float* BsBase = smem + STAGES * A_ELE;
    uint32_t smem_u32 = (uint32_t)__cvta_generic_to_shared(smem);
    uint32_t As_u32 = smem_u32;
    uint32_t Bs_u32 = smem_u32 + STAGES * A_ELE * 4;

    const int tid = threadIdx.x;
    const int lane = tid & 31;
    const int warp = tid >> 5;
    const int wm = (warp / WN_WARPS) * (MT * 16);
    const int wn = (warp % WN_WARPS) * 32;
    const int g = lane >> 2;
    const int tq = lane & 3;
    const int rowBase = blockIdx.y * 128;
    const int colBase = blockIdx.x * BN;
    const int KT = K / 32;

    float acc[MT][4][4];
#pragma unroll
    for (int i = 0; i < MT; i++)
#pragma unroll
        for (int j = 0; j < 4; j++)
#pragma unroll
            for (int q = 0; q < 4; q++) acc[i][j][q] = 0.0f;

    const int a_m = tid >> 3;
    const int a_kq = tid & 7;

    auto issue = [&](int stage, int kt) {
        const int k0 = kt * 32;
#pragma unroll
        for (int i = 0; i < 4; i++) {
            int m = a_m + i * 32;
            const float* gsrc = A + (size_t)(rowBase + m) * K + k0 + a_kq * 4;
            uint32_t sdst = As_u32 + (stage * A_ELE + m * AS_STRIDE + a_kq * 4) * 4;
            cp_async16(sdst, gsrc, (rowBase + m < M) ? 16 : 0);
        }
#pragma unroll
        for (int i = 0; i < B_PER; i++) {
            int idx = tid + i * 256;
            int kk = idx / NQ;
            int nq = idx % NQ;
            int gn = colBase + nq * 4;
            const float* gsrc = W + (size_t)(k0 + kk) * N + gn;
            uint32_t sdst = Bs_u32 + (stage * B_ELE + kk * BS_STRIDE + nq * 4) * 4;
            cp_async16(sdst, gsrc, (gn + 3 < N) ? 16 : 0);
        }
    };

#pragma unroll
    for (int p = 0; p < 2; p++) {
        if (p < KT) issue(p, p);
        asm volatile("cp.async.commit_group;\n" ::: "memory");
    }

    for (int kt = 0; kt < KT; kt++) {
        asm volatile("cp.async.wait_group 1;\n" ::: "memory");
        __syncthreads();

        const float* As = AsBase + (kt % STAGES) * A_ELE;
        const float* Bs = BsBase + (kt % STAGES) * B_ELE;
#pragma unroll
        for (int ks = 0; ks < 4; ks++) {
            const int kb = ks * 8;
            unsigned a[MT][4], b[4][2];
#pragma unroll
            for (int mt = 0; mt < MT; mt++) {
                int r = wm + mt * 16 + g;
                a[mt][0] = __float_as_uint(As[r * AS_STRIDE + kb + tq]);
                a[mt][1] = __float_as_uint(As[(r + 8) * AS_STRIDE + kb + tq]);
                a[mt][2] = __float_as_uint(As[r * AS_STRIDE + kb + tq + 4]);
                a[mt][3] = __float_as_uint(As[(r + 8) * AS_STRIDE + kb + tq + 4]);
            }
#pragma unroll
            for (int nt = 0; nt < 4; nt++) {
                int n = wn + nt * 8 + g;
                b[nt][0] = __float_as_uint(Bs[(kb + tq) * BS_STRIDE + n]);
                b[nt][1] = __float_as_uint(Bs[(kb + tq + 4) * BS_STRIDE + n]);
            }
#pragma unroll
            for (int mt = 0; mt < MT; mt++)
#pragma unroll
                for (int nt = 0; nt < 4; nt++) {
                    asm volatile(
                        "mma.sync.aligned.m16n8k8.row.col.f32.tf32.tf32.f32 "
                        "{%0,%1,%2,%3}, {%4,%5,%6,%7}, {%8,%9}, {%0,%1,%2,%3};"
                        : "+f"(acc[mt][nt][0]), "+f"(acc[mt][nt][1]),
                          "+f"(acc[mt][nt][2]), "+f"(acc[mt][nt][3])
                        : "r"(a[mt][0]), "r"(a[mt][1]), "r"(a[mt][2]), "r"(a[mt][3]),
                          "r"(b[nt][0]), "r"(b[nt][1]));
                }
        }
        if (kt + 2 < KT) issue((kt + 2) % STAGES, kt + 2);
        asm volatile("cp.async.commit_group;\n" ::: "memory");
    }

#pragma unroll
    for (int mt = 0; mt < MT; mt++) {
        int r0 = rowBase + wm + mt * 16 + g;
        int r1 = r0 + 8;
        float rs0 = 1.f, rs1 = 1.f, ws0 = 1.f, ws1 = 1.f;
        if (rs) {
            if (r0 < M) rs0 = rs[r0];
            if (r1 < M) rs1 = rs[r1];
        }
        if (ws) {
            if (r0 < M) ws0 = ws[r0];
            if (r1 < M) ws1 = ws[r1];
        }
#pragma unroll
        for (int nt = 0; nt < 4; nt++) {
            int c = colBase + wn + nt * 8 + 2 * tq;
            float bx = (c < N) ? bias[c] : 0.f;
            float by = (c + 1 < N) ? bias[c + 1] : 0.f;
            if (r0 < M) {
                float vx = ws0 * fmaxf(acc[mt][nt][0] * rs0 + bx, 0.f);
                float vy = ws0 * fmaxf(acc[mt][nt][1] * rs0 + by, 0.f);
                if (c + 1 < N) *(float2*)(C + (size_t)r0 * N + c) = make_float2(vx, vy);
                else if (c < N) C[(size_t)r0 * N + c] = vx;
            }
            if (r1 < M) {
                float vx = ws1 * fmaxf(acc[mt][nt][2] * rs1 + bx, 0.f);
                float vy = ws1 * fmaxf(acc[mt][nt][3] * rs1 + by, 0.f);
                if (c + 1 < N) *(float2*)(C + (size_t)r1 * N + c) = make_float2(vx, vy);
                else if (c < N) C[(size_t)r1 * N + c] = vx;
            }
        }
    }
}

// ---------------- host orchestration ---------------------------------------
extern "C" void kernel_launch(void* const* d_in, const int* in_sizes, int n_in,
                              void* d_out, int out_size) {
    const float* x   = (const float*)d_in[0];
    const int* src   = (const int*)d_in[1];
    const int* dst   = (const int*)d_in[2];
    const float* W1  = (const float*)d_in[3];
    const float* b1  = (const float*)d_in[4];
    const float* W2  = (const float*)d_in[5];
    const float* b2  = (const float*)d_in[6];
    const float* W3  = (const float*)d_in[7];
    const float* b3  = (const float*)d_in[8];
    const float* Wg1 = (const float*)d_in[9];
    const float* bg1 = (const float*)d_in[10];
    const float* Wg2 = (const float*)d_in[11];
    const float* bg2 = (const float*)d_in[12];
    const float* Wg3 = (const float*)d_in[13];
    const float* bg3 = (const float*)d_in[14];
    const float* Wg4 = (const float*)d_in[15];
    const float* bg4 = (const float*)d_in[16];
    float* out = (float*)d_out;

    float *h1, *h2, *hA, *hB, *degf, *nrm;
    int *cnt, *rowptr, *cursor, *bsum, *col;
    __half *w1t, *w2t;
    cudaGetSymbolAddress((void**)&h1, g_h1);
    cudaGetSymbolAddress((void**)&h2, g_h2);
    cudaGetSymbolAddress((void**)&hA, g_hA);
    cudaGetSymbolAddress((void**)&hB, g_hB);
    cudaGetSymbolAddress((void**)&degf, g_degf);
    cudaGetSymbolAddress((void**)&nrm, g_nrm);
    cudaGetSymbolAddress((void**)&cnt, g_cnt);
    cudaGetSymbolAddress((void**)&rowptr, g_rowptr);
    cudaGetSymbolAddress((void**)&cursor, g_cursor);
    cudaGetSymbolAddress((void**)&bsum, g_bsum);
    cudaGetSymbolAddress((void**)&col, g_col);
    cudaGetSymbolAddress((void**)&w1t, g_w1t);
    cudaGetSymbolAddress((void**)&w2t, g_w2t);

    __half* xh  = (__half*)h2;   // x fp16 staged in g_h2 (dead until GEMM2 writes h2)
    __half* h1h = (__half*)h1;   // h1 stored fp16 in g_h1

    const float* nsrc = nrm;
    const float* ndst = nrm + NN;

    constexpr int SMEM64  = 3 * (128 * 36 + 32 * 72) * 4;
    constexpr int SMEMF16 = 3 * (2 * 128 * 40 * 2);
    cudaFuncSetAttribute(gemm_tf32<64>, cudaFuncAttributeMaxDynamicSharedMemorySize, SMEM64);
    cudaFuncSetAttribute(gemm_f16<true>, cudaFuncAttributeMaxDynamicSharedMemorySize, SMEMF16);
    cudaFuncSetAttribute(gemm_f16<false>, cudaFuncAttributeMaxDynamicSharedMemorySize, SMEMF16);

    // degrees + norms + CSR + fp16 prep
    zero_f<<<(NN + 255) / 256, 256>>>(degf, NN);
    zero_i<<<(NN + 255) / 256, 256>>>(cnt, NN);
    deg_src_kernel<<<(NE + 255) / 256, 256>>>(src, degf);
    hist_dst_kernel<<<(NE + 255) / 256, 256>>>(dst, cnt);
    norm_kernel<<<(NN + 255) / 256, 256>>>(degf, cnt, nrm);
    scan1<<<NB_SCAN, 1024>>>(cnt, rowptr, bsum);
    scan2<<<1, 128>>>(bsum);
    scan3<<<NB_SCAN, 1024>>>(rowptr, bsum, cursor);
    fill_csr<<<(NE + 255) / 256, 256>>>(src, dst, cursor, col);
    wcvt_kernel<<<(512 * 512 + 255) / 256, 256>>>(W1, w1t, 512, 512);
    wcvt_kernel<<<(512 * 256 + 255) / 256, 256>>>(W2, w2t, 512, 256);
    cvt_f2h<<<(NN * 512 / 4 + 255) / 256, 256>>>(x, xh, NN * 512 / 4);

    const int M = NN;
    const int NYT = (M + 127) / 128;   // 782

    // MLP layer 1: fp16 TC [100k,512]@[512,512] -> h1 (fp16)
    gemm_f16<true><<<dim3(4, NYT), 256, SMEMF16>>>(xh, w1t, b1, h1h, M, 512, 512);
    // MLP layer 2: fp16 TC [100k,512]@[512,256] -> h2 (fp32)
    gemm_f16<false><<<dim3(2, NYT), 256, SMEMF16>>>(h1h, w2t, b2, h2, M, 256, 512);
    // MLP layer 3: [100k,256]@[256,64] tf32, output pre-scaled by norm_src
    dim3 gS(1, NYT);
    gemm_tf32<64><<<gS, 256, SMEM64>>>(h2, W3, b3, nullptr, nsrc, hA, M, 64, 256);

    const int gatherBlocks = (NN + 15) / 16;

    gather_csr<<<gatherBlocks, 256>>>(hA, rowptr, col, hB);
    gemm_tf32<64><<<gS, 256, SMEM64>>>(hB, Wg1, bg1, ndst, nsrc, hA, M, 64, 64);

    gather_csr<<<gatherBlocks, 256>>>(hA, rowptr, col, hB);
    gemm_tf32<64><<<gS, 256, SMEM64>>>(hB, Wg2, bg2, ndst, nsrc, hA, M, 64, 64);

    gather_csr<<<gatherBlocks, 256>>>(hA, rowptr, col, hB);
    gemm_tf32<64><<<gS, 256, SMEM64>>>(hB, Wg3, bg3, ndst, nsrc, hA, M, 64, 64);

    gather_csr<<<gatherBlocks, 256>>>(hA, rowptr, col, hB);
    gemm_tf32<64><<<gS, 256, SMEM64>>>(hB, Wg4, bg4, ndst, nullptr, out, M, 40, 64);
}

// round 6
// speedup vs baseline: 5.7272x; 1.0678x over previous
#include <cuda_runtime.h>
#include <cuda_fp16.h>
#include <cstdint>

#define NN 100000
#define NE 1600000
#define NB_SCAN 98   // ceil(NN/1024)

// ---------------- scratch (device globals; no allocation allowed) ----------
__device__ float g_h1[(size_t)NN * 512];   // h1 as fp16 (aliased)
__device__ float g_h2[(size_t)NN * 256];   // xh (fp16) first, then h2 fp16
__device__ float g_hA[(size_t)NN * 64];    // fp16 node features (aliased)
__device__ float g_hB[(size_t)NN * 64];    // fp16 agg (aliased)
__device__ float g_degf[NN];
__device__ float g_nrm[2 * NN];      // [0..NN)=norm_src, [NN..2NN)=norm_dst
__device__ int   g_cnt[NN];
__device__ int   g_rowptr[NN];
__device__ int   g_cursor[NN];
__device__ int   g_bsum[128];
__device__ int   g_col[NE];
// transposed fp16 weights: Wt[n][k] = W[k][n]
__device__ __half g_w1t[512 * 512];
__device__ __half g_w2t[256 * 512];
__device__ __half g_w3t[64 * 256];
__device__ __half g_wgt[4][64 * 64];   // Wg1..Wg4 (Wg4 zero-padded to 64 rows)

// ---------------- utility kernels -------------------------------------------
__global__ void zero_f(float* __restrict__ p, int n) {
    int i = blockIdx.x * blockDim.x + threadIdx.x;
    if (i < n) p[i] = 0.0f;
}
__global__ void zero_i(int* __restrict__ p, int n) {
    int i = blockIdx.x * blockDim.x + threadIdx.x;
    if (i < n) p[i] = 0;
}
__global__ void deg_src_kernel(const int* __restrict__ src, float* __restrict__ degf) {
    int e = blockIdx.x * blockDim.x + threadIdx.x;
    if (e < NE) atomicAdd(&degf[src[e]], 1.0f);
}
__global__ void hist_dst_kernel(const int* __restrict__ dst, int* __restrict__ cnt) {
    int e = blockIdx.x * blockDim.x + threadIdx.x;
    if (e < NE) atomicAdd(&cnt[dst[e]], 1);
}
__global__ void norm_kernel(const float* __restrict__ degf, const int* __restrict__ cnt,
                            float* __restrict__ nrm) {
    int i = blockIdx.x * blockDim.x + threadIdx.x;
    if (i < NN) {
        nrm[i] = rsqrtf(fmaxf(degf[i], 1.0f));
        nrm[NN + i] = rsqrtf(fmaxf((float)cnt[i], 1.0f));
    }
}

__device__ __forceinline__ uint32_t packh2(float lo, float hi) {
    uint32_t r;
    asm("cvt.rn.f16x2.f32 %0, %1, %2;" : "=r"(r) : "f"(hi), "f"(lo));
    return r;
}

// fp32 -> fp16 bulk convert (4 elems/thread)
__global__ void cvt_f2h(const float* __restrict__ in, __half* __restrict__ out, int n4) {
    int i = blockIdx.x * blockDim.x + threadIdx.x;
    if (i < n4) {
        float4 v = ((const float4*)in)[i];
        uint2 o;
        o.x = packh2(v.x, v.y);
        o.y = packh2(v.z, v.w);
        ((uint2*)out)[i] = o;
    }
}

// W [K,N] fp32 -> Wt [Npad,K] fp16 (transpose + convert, zero-pad rows >= N)
__global__ void wcvt_kernel(const float* __restrict__ W, __half* __restrict__ Wt,
                            int K, int N, int Npad) {
    int i = blockIdx.x * blockDim.x + threadIdx.x;
    if (i < Npad * K) {
        int n = i / K, k = i % K;
        Wt[i] = (n < N) ? __float2half(W[(size_t)k * N + n]) : __half(0.f);
    }
}

// ---------------- CSR build --------------------------------------------------
__global__ void scan1(const int* __restrict__ cnt, int* __restrict__ excl,
                      int* __restrict__ bsum) {
    __shared__ int sh[1024];
    int tid = threadIdx.x;
    int i = blockIdx.x * 1024 + tid;
    int v = (i < NN) ? cnt[i] : 0;
    sh[tid] = v;
    __syncthreads();
    for (int off = 1; off < 1024; off <<= 1) {
        int t = (tid >= off) ? sh[tid - off] : 0;
        __syncthreads();
        sh[tid] += t;
        __syncthreads();
    }
    if (i < NN) excl[i] = sh[tid] - v;
    if (tid == 1023) bsum[blockIdx.x] = sh[1023];
}
__global__ void scan2(int* __restrict__ bsum) {
    __shared__ int sh[128];
    int tid = threadIdx.x;
    int v = (tid < NB_SCAN) ? bsum[tid] : 0;
    sh[tid] = v;
    __syncthreads();
    for (int off = 1; off < 128; off <<= 1) {
        int t = (tid >= off) ? sh[tid - off] : 0;
        __syncthreads();
        sh[tid] += t;
        __syncthreads();
    }
    if (tid < NB_SCAN) bsum[tid] = sh[tid] - v;
}
__global__ void scan3(int* __restrict__ excl, const int* __restrict__ bsum,
                      int* __restrict__ cursor) {
    int i = blockIdx.x * 1024 + threadIdx.x;
    if (i < NN) {
        int r = excl[i] + bsum[blockIdx.x];
        excl[i] = r;
        cursor[i] = r;
    }
}
__global__ void fill_csr(const int* __restrict__ src, const int* __restrict__ dst,
                         int* __restrict__ cursor, int* __restrict__ col) {
    int e = blockIdx.x * blockDim.x + threadIdx.x;
    if (e < NE) {
        int p = atomicAdd(&cursor[dst[e]], 1);
        col[p] = src[e];
    }
}

// ---------------- CSR gather (fp16 rows, fp32 accumulate) --------------------
// 8 lanes per node; each lane owns 8 halves (16B) of the 64-wide row.
__global__ void gather_h(const __half* __restrict__ h, const int* __restrict__ rowptr,
                         const int* __restrict__ col, __half* __restrict__ agg) {
    int t = threadIdx.x;
    int node = blockIdx.x * 32 + (t >> 3);
    if (node >= NN) return;
    int c = t & 7;
    int beg = rowptr[node];
    int end = (node == NN - 1) ? NE : rowptr[node + 1];
    float acc[8] = {0.f, 0.f, 0.f, 0.f, 0.f, 0.f, 0.f, 0.f};
    for (int i = beg; i < end; i++) {
        int s = __ldg(&col[i]);
        uint4 v = ((const uint4*)(h + (size_t)s * 64))[c];
        const __half2* hv = (const __half2*)&v;
#pragma unroll
        for (int j = 0; j < 4; j++) {
            float2 f = __half22float2(hv[j]);
            acc[2 * j] += f.x;
            acc[2 * j + 1] += f.y;
        }
    }
    uint4 o;
    o.x = packh2(acc[0], acc[1]);
    o.y = packh2(acc[2], acc[3]);
    o.z = packh2(acc[4], acc[5]);
    o.w = packh2(acc[6], acc[7]);
    ((uint4*)(agg + (size_t)node * 64))[c] = o;
}

// ---------------- common async copy helper ----------------------------------
__device__ __forceinline__ void cp_async16(uint32_t saddr, const void* gaddr, int sz) {
    asm volatile("cp.async.cg.shared.global [%0], [%1], 16, %2;\n"
                 :: "r"(saddr), "l"(gaddr), "r"(sz));
}

// ============================================================================
// fp16 tensor-core GEMM (wide): C = relu(A @ Wt^T + b), tile 128x128x32
// ============================================================================
template <bool OUT_HALF>
__global__ void __launch_bounds__(256, 2)
gemm_f16(const __half* __restrict__ A, const __half* __restrict__ Wt,
         const float* __restrict__ bias, void* __restrict__ Cout,
         int M, int N, int K) {
    constexpr int STRIDE_H = 40;
    constexpr int A_BYTES = 128 * STRIDE_H * 2;
    constexpr int STAGE_BYTES = 2 * A_BYTES;
    extern __shared__ char dsm[];
    uint32_t smem_u = (uint32_t)__cvta_generic_to_shared(dsm);

    const int tid = threadIdx.x;
    const int lane = tid & 31;
    const int warp = tid >> 5;
    const int wm = (warp >> 2) * 64;
    const int wn = (warp & 3) * 32;
    const int rowBase = blockIdx.y * 128;
    const int colBase = blockIdx.x * 128;
    const int KT = K / 32;

    const int lrow = lane & 7;
    const int sub = lane >> 3;
    const int subB = sub & 1;

    float acc[4][4][4];
#pragma unroll
    for (int i = 0; i < 4; i++)
#pragma unroll
        for (int j = 0; j < 4; j++)
#pragma unroll
            for (int q = 0; q < 4; q++) acc[i][j][q] = 0.0f;

    const int l_m = tid >> 2;
    const int l_c = tid & 3;
    auto issue = [&](int stage, int kt) {
        const int k0 = kt * 32;
        uint32_t base = smem_u + stage * STAGE_BYTES;
#pragma unroll
        for (int i = 0; i < 2; i++) {
            int m = l_m + i * 64;
            const __half* gsrc = A + (size_t)(rowBase + m) * K + k0 + l_c * 8;
            cp_async16(base + m * 80 + l_c * 16, gsrc, (rowBase + m < M) ? 16 : 0);
        }
#pragma unroll
        for (int i = 0; i < 2; i++) {
            int n = l_m + i * 64;
            const __half* gsrc = Wt + (size_t)(colBase + n) * K + k0 + l_c * 8;
            cp_async16(base + A_BYTES + n * 80 + l_c * 16, gsrc, 16);
        }
    };

#pragma unroll
    for (int p = 0; p < 2; p++) {
        issue(p, p);
        asm volatile("cp.async.commit_group;\n" ::: "memory");
    }

    for (int kt = 0; kt < KT; kt++) {
        asm volatile("cp.async.wait_group 1;\n" ::: "memory");
        __syncthreads();
        const int stage = kt % 3;
        uint32_t As_u = smem_u + stage * STAGE_BYTES;
        uint32_t Bs_u = As_u + A_BYTES;

#pragma unroll
        for (int ks = 0; ks < 2; ks++) {
            const int kb = ks * 16;
            uint32_t a[4][4], b[4][2];
#pragma unroll
            for (int mt = 0; mt < 4; mt++) {
                int r = wm + mt * 16 + (sub & 1) * 8 + lrow;
                uint32_t addr = As_u + (r * STRIDE_H + kb + (sub >> 1) * 8) * 2;
                asm volatile(
                    "ldmatrix.sync.aligned.m8n8.x4.shared.b16 {%0,%1,%2,%3}, [%4];"
                    : "=r"(a[mt][0]), "=r"(a[mt][1]), "=r"(a[mt][2]), "=r"(a[mt][3])
                    : "r"(addr));
            }
#pragma unroll
            for (int nt = 0; nt < 4; nt++) {
                int n = wn + nt * 8 + lrow;
                uint32_t addr = Bs_u + (n * STRIDE_H + kb + subB * 8) * 2;
                asm volatile(
                    "ldmatrix.sync.aligned.m8n8.x2.shared.b16 {%0,%1}, [%2];"
                    : "=r"(b[nt][0]), "=r"(b[nt][1]) : "r"(addr));
            }
#pragma unroll
            for (int mt = 0; mt < 4; mt++)
#pragma unroll
                for (int nt = 0; nt < 4; nt++) {
                    asm volatile(
                        "mma.sync.aligned.m16n8k16.row.col.f32.f16.f16.f32 "
                        "{%0,%1,%2,%3}, {%4,%5,%6,%7}, {%8,%9}, {%0,%1,%2,%3};"
                        : "+f"(acc[mt][nt][0]), "+f"(acc[mt][nt][1]),
                          "+f"(acc[mt][nt][2]), "+f"(acc[mt][nt][3])
                        : "r"(a[mt][0]), "r"(a[mt][1]), "r"(a[mt][2]), "r"(a[mt][3]),
                          "r"(b[nt][0]), "r"(b[nt][1]));
                }
        }
        if (kt + 2 < KT) issue((kt + 2) % 3, kt + 2);
        asm volatile("cp.async.commit_group;\n" ::: "memory");
    }

    const int g = lane >> 2;
    const int tq = lane & 3;
#pragma unroll
    for (int mt = 0; mt < 4; mt++) {
        int r0 = rowBase + wm + mt * 16 + g;
        int r1 = r0 + 8;
#pragma unroll
        for (int nt = 0; nt < 4; nt++) {
            int c = colBase + wn + nt * 8 + 2 * tq;
            float bx = __ldg(&bias[c]);
            float by = __ldg(&bias[c + 1]);
            if (r0 < M) {
                float vx = fmaxf(acc[mt][nt][0] + bx, 0.f);
                float vy = fmaxf(acc[mt][nt][1] + by, 0.f);
                if (OUT_HALF)
                    *(uint32_t*)((__half*)Cout + (size_t)r0 * N + c) = packh2(vx, vy);
                else
                    *(float2*)((float*)Cout + (size_t)r0 * N + c) = make_float2(vx, vy);
            }
            if (r1 < M) {
                float vx = fmaxf(acc[mt][nt][2] + bx, 0.f);
                float vy = fmaxf(acc[mt][nt][3] + by, 0.f);
                if (OUT_HALF)
                    *(uint32_t*)((__half*)Cout + (size_t)r1 * N + c) = packh2(vx, vy);
                else
                    *(float2*)((float*)Cout + (size_t)r1 * N + c) = make_float2(vx, vy);
            }
        }
    }
}

// ============================================================================
// fp16 tensor-core GEMM (narrow): tile 128x64, BK=64, row scales rs/ws.
// C[r,:] = ws[r] * relu( rs[r]*(A@Wt^T)[r,:] + b )
// Wt must have 64 valid rows (zero-padded if N<64). N <= 64.
// ============================================================================
template <bool OUT_HALF>
__global__ void __launch_bounds__(256, 2)
gemm_f16_s(const __half* __restrict__ A, const __half* __restrict__ Wt,
           const float* __restrict__ bias, const float* __restrict__ rs,
           const float* __restrict__ ws, void* __restrict__ Cout,
           int M, int N, int K) {
    constexpr int STRIDE_H = 72;                  // 64 + 8 pad halves (144B rows)
    constexpr int A_BYTES = 128 * STRIDE_H * 2;   // 18432
    constexpr int B_BYTES = 64 * STRIDE_H * 2;    // 9216
    constexpr int STAGE_BYTES = A_BYTES + B_BYTES;
    extern __shared__ char dsm[];
    uint32_t smem_u = (uint32_t)__cvta_generic_to_shared(dsm);

    const int tid = threadIdx.x;
    const int lane = tid & 31;
    const int warp = tid >> 5;
    const int wm = (warp >> 1) * 32;    // 4 row groups of 32
    const int wn = (warp & 1) * 32;     // 2 col groups of 32
    const int rowBase = blockIdx.y * 128;
    const int KT = K / 64;

    const int lrow = lane & 7;
    const int sub = lane >> 3;
    const int subB = sub & 1;

    float acc[2][4][4];
#pragma unroll
    for (int i = 0; i < 2; i++)
#pragma unroll
        for (int j = 0; j < 4; j++)
#pragma unroll
            for (int q = 0; q < 4; q++) acc[i][j][q] = 0.0f;

    const int l_r = tid >> 1;          // A: 2 chunks of 16B per 128B row-half
    const int l_c = tid & 1;
    auto issue = [&](int stage, int kt) {
        const int k0 = kt * 64;
        uint32_t base = smem_u + stage * STAGE_BYTES;
        // A: 128 rows x 64 halves (128B) = 4 chunks/row, 256 threads x 4 iter
#pragma unroll
        for (int i = 0; i < 4; i++) {
            int idx = tid + i * 256;
            int m = idx >> 3;
            int cq = idx & 7;
            const __half* gsrc = A + (size_t)(rowBase + m) * K + k0 + cq * 8;
            cp_async16(base + m * 144 + cq * 16, gsrc, (rowBase + m < M) ? 16 : 0);
        }
        // B: 64 rows x 64 halves = 512 chunks, 2 iters
#pragma unroll
        for (int i = 0; i < 2; i++) {
            int idx = tid + i * 256;
            int n = idx >> 3;
            int cq = idx & 7;
            const __half* gsrc = Wt + (size_t)n * K + k0 + cq * 8;
            cp_async16(base + A_BYTES + n * 144 + cq * 16, gsrc, 16);
        }
    };

#pragma unroll
    for (int p = 0; p < 2; p++) {
        if (p < KT) issue(p, p);
        asm volatile("cp.async.commit_group;\n" ::: "memory");
    }

    for (int kt = 0; kt < KT; kt++) {
        asm volatile("cp.async.wait_group 1;\n" ::: "memory");
        __syncthreads();
        const int stage = kt % 3;
        uint32_t As_u = smem_u + stage * STAGE_BYTES;
        uint32_t Bs_u = As_u + A_BYTES;

#pragma unroll
        for (int ks = 0; ks < 4; ks++) {
            const int kb = ks * 16;
            uint32_t a[2][4], b[4][2];
#pragma unroll
            for (int mt = 0; mt < 2; mt++) {
                int r = wm + mt * 16 + (sub & 1) * 8 + lrow;
                uint32_t addr = As_u + (r * STRIDE_H + kb + (sub >> 1) * 8) * 2;
                asm volatile(
                    "ldmatrix.sync.aligned.m8n8.x4.shared.b16 {%0,%1,%2,%3}, [%4];"
                    : "=r"(a[mt][0]), "=r"(a[mt][1]), "=r"(a[mt][2]), "=r"(a[mt][3])
                    : "r"(addr));
            }
#pragma unroll
            for (int nt = 0; nt < 4; nt++) {
                int n = wn + nt * 8 + lrow;
                uint32_t addr = Bs_u + (n * STRIDE_H + kb + subB * 8) * 2;
                asm volatile(
                    "ldmatrix.sync.aligned.m8n8.x2.shared.b16 {%0,%1}, [%2];"
                    : "=r"(b[nt][0]), "=r"(b[nt][1]) : "r"(addr));
            }
#pragma unroll
            for (int mt = 0; mt < 2; mt++)
#pragma unroll
                for (int nt = 0; nt < 4; nt++) {
                    asm volatile(
                        "mma.sync.aligned.m16n8k16.row.col.f32.f16.f16.f32 "
                        "{%0,%1,%2,%3}, {%4,%5,%6,%7}, {%8,%9}, {%0,%1,%2,%3};"
                        : "+f"(acc[mt][nt][0]), "+f"(acc[mt][nt][1]),
                          "+f"(acc[mt][nt][2]), "+f"(acc[mt][nt][3])
                        : "r"(a[mt][0]), "r"(a[mt][1]), "r"(a[mt][2]), "r"(a[mt][3]),
                          "r"(b[nt][0]), "r"(b[nt][1]));
                }
        }
        if (kt + 2 < KT) issue((kt + 2) % 3, kt + 2);
        asm volatile("cp.async.commit_group;\n" ::: "memory");
    }

    const int g = lane >> 2;
    const int tq = lane & 3;
#pragma unroll
    for (int mt = 0; mt < 2; mt++) {
        int r0 = rowBase + wm + mt * 16 + g;
        int r1 = r0 + 8;
        float rs0 = 1.f, rs1 = 1.f, ws0 = 1.f, ws1 = 1.f;
        if (rs) {
            if (r0 < M) rs0 = rs[r0];
            if (r1 < M) rs1 = rs[r1];
        }
        if (ws) {
            if (r0 < M) ws0 = ws[r0];
            if (r1 < M) ws1 = ws[r1];
        }
#pragma unroll
        for (int nt = 0; nt < 4; nt++) {
            int c = wn + nt * 8 + 2 * tq;
            float bx = (c < N) ? __ldg(&bias[c]) : 0.f;
            float by = (c + 1 < N) ? __ldg(&bias[c + 1]) : 0.f;
            if (r0 < M) {
                float vx = ws0 * fmaxf(acc[mt][nt][0] * rs0 + bx, 0.f);
                float vy = ws0 * fmaxf(acc[mt][nt][1] * rs0 + by, 0.f);
                if (OUT_HALF) {
                    if (c + 1 < N)
                        *(uint32_t*)((__half*)Cout + (size_t)r0 * N + c) = packh2(vx, vy);
                } else {
                    if (c + 1 < N)
                        *(float2*)((float*)Cout + (size_t)r0 * N + c) = make_float2(vx, vy);
                    else if (c < N)
                        ((float*)Cout)[(size_t)r0 * N + c] = vx;
                }
            }
            if (r1 < M) {
                float vx = ws1 * fmaxf(acc[mt][nt][2] * rs1 + bx, 0.f);
                float vy = ws1 * fmaxf(acc[mt][nt][3] * rs1 + by, 0.f);
                if (OUT_HALF) {
                    if (c + 1 < N)
                        *(uint32_t*)((__half*)Cout + (size_t)r1 * N + c) = packh2(vx, vy);
                } else {
                    if (c + 1 < N)
                        *(float2*)((float*)Cout + (size_t)r1 * N + c) = make_float2(vx, vy);
                    else if (c < N)
                        ((float*)Cout)[(size_t)r1 * N + c] = vx;
                }
            }
        }
    }
}

// ---------------- host orchestration ---------------------------------------
extern "C" void kernel_launch(void* const* d_in, const int* in_sizes, int n_in,
                              void* d_out, int out_size) {
    const float* x   = (const float*)d_in[0];
    const int* src   = (const int*)d_in[1];
    const int* dst   = (const int*)d_in[2];
    const float* W1  = (const float*)d_in[3];
    const float* b1  = (const float*)d_in[4];
    const float* W2  = (const float*)d_in[5];
    const float* b2  = (const float*)d_in[6];
    const float* W3  = (const float*)d_in[7];
    const float* b3  = (const float*)d_in[8];
    const float* Wg1 = (const float*)d_in[9];
    const float* bg1 = (const float*)d_in[10];
    const float* Wg2 = (const float*)d_in[11];
    const float* bg2 = (const float*)d_in[12];
    const float* Wg3 = (const float*)d_in[13];
    const float* bg3 = (const float*)d_in[14];
    const float* Wg4 = (const float*)d_in[15];
    const float* bg4 = (const float*)d_in[16];
    float* out = (float*)d_out;

    float *h1, *h2, *hA, *hB, *degf, *nrm;
    int *cnt, *rowptr, *cursor, *bsum, *col;
    __half *w1t, *w2t, *w3t, *wgt;
    cudaGetSymbolAddress((void**)&h1, g_h1);
    cudaGetSymbolAddress((void**)&h2, g_h2);
    cudaGetSymbolAddress((void**)&hA, g_hA);
    cudaGetSymbolAddress((void**)&hB, g_hB);
    cudaGetSymbolAddress((void**)&degf, g_degf);
    cudaGetSymbolAddress((void**)&nrm, g_nrm);
    cudaGetSymbolAddress((void**)&cnt, g_cnt);
    cudaGetSymbolAddress((void**)&rowptr, g_rowptr);
    cudaGetSymbolAddress((void**)&cursor, g_cursor);
    cudaGetSymbolAddress((void**)&bsum, g_bsum);
    cudaGetSymbolAddress((void**)&col, g_col);
    cudaGetSymbolAddress((void**)&w1t, g_w1t);
    cudaGetSymbolAddress((void**)&w2t, g_w2t);
    cudaGetSymbolAddress((void**)&w3t, g_w3t);
    cudaGetSymbolAddress((void**)&wgt, g_wgt);

    __half* xh  = (__half*)h2;   // x fp16 staged in g_h2 (dead after GEMM1)
    __half* h1h = (__half*)h1;
    __half* h2h = (__half*)h2;   // reuses g_h2 after GEMM1 consumed xh
    __half* hAh = (__half*)hA;
    __half* hBh = (__half*)hB;

    const float* nsrc = nrm;
    const float* ndst = nrm + NN;

    constexpr int SMEMF16 = 3 * (2 * 128 * 40 * 2);
    constexpr int SMEMS   = 3 * ((128 + 64) * 72 * 2);
    cudaFuncSetAttribute(gemm_f16<true>,  cudaFuncAttributeMaxDynamicSharedMemorySize, SMEMF16);
    cudaFuncSetAttribute(gemm_f16<false>, cudaFuncAttributeMaxDynamicSharedMemorySize, SMEMF16);
    cudaFuncSetAttribute(gemm_f16_s<true>,  cudaFuncAttributeMaxDynamicSharedMemorySize, SMEMS);
    cudaFuncSetAttribute(gemm_f16_s<false>, cudaFuncAttributeMaxDynamicSharedMemorySize, SMEMS);

    // degrees + norms + CSR + fp16 prep
    zero_f<<<(NN + 255) / 256, 256>>>(degf, NN);
    zero_i<<<(NN + 255) / 256, 256>>>(cnt, NN);
    deg_src_kernel<<<(NE + 255) / 256, 256>>>(src, degf);
    hist_dst_kernel<<<(NE + 255) / 256, 256>>>(dst, cnt);
    norm_kernel<<<(NN + 255) / 256, 256>>>(degf, cnt, nrm);
    scan1<<<NB_SCAN, 1024>>>(cnt, rowptr, bsum);
    scan2<<<1, 128>>>(bsum);
    scan3<<<NB_SCAN, 1024>>>(rowptr, bsum, cursor);
    fill_csr<<<(NE + 255) / 256, 256>>>(src, dst, cursor, col);
    wcvt_kernel<<<(512 * 512 + 255) / 256, 256>>>(W1, w1t, 512, 512, 512);
    wcvt_kernel<<<(512 * 256 + 255) / 256, 256>>>(W2, w2t, 512, 256, 256);
    wcvt_kernel<<<(256 * 64 + 255) / 256, 256>>>(W3, w3t, 256, 64, 64);
    wcvt_kernel<<<(64 * 64 + 255) / 256, 256>>>(Wg1, wgt + 0 * 4096, 64, 64, 64);
    wcvt_kernel<<<(64 * 64 + 255) / 256, 256>>>(Wg2, wgt + 1 * 4096, 64, 64, 64);
    wcvt_kernel<<<(64 * 64 + 255) / 256, 256>>>(Wg3, wgt + 2 * 4096, 64, 64, 64);
    wcvt_kernel<<<(64 * 64 + 255) / 256, 256>>>(Wg4, wgt + 3 * 4096, 64, 40, 64);
    cvt_f2h<<<(NN * 512 / 4 + 255) / 256, 256>>>(x, xh, NN * 512 / 4);

    const int M = NN;
    const int NYT = (M + 127) / 128;   // 782
    dim3 gS(1, NYT);

    // MLP layer 1: fp16 TC -> h1 (fp16)
    gemm_f16<true><<<dim3(4, NYT), 256, SMEMF16>>>(xh, w1t, b1, h1h, M, 512, 512);
    // MLP layer 2: fp16 TC -> h2 (fp16)
    gemm_f16<true><<<dim3(2, NYT), 256, SMEMF16>>>(h1h, w2t, b2, h2h, M, 256, 512);
    // MLP layer 3: fp16 TC narrow -> hA (fp16), output scaled by norm_src
    gemm_f16_s<true><<<gS, 256, SMEMS>>>(h2h, w3t, b3, nullptr, nsrc, hAh, M, 64, 256);

    const int gatherBlocks = (NN + 31) / 32;

    gather_h<<<gatherBlocks, 256>>>(hAh, rowptr, col, hBh);
    gemm_f16_s<true><<<gS, 256, SMEMS>>>(hBh, wgt + 0 * 4096, bg1, ndst, nsrc, hAh, M, 64, 64);

    gather_h<<<gatherBlocks, 256>>>(hAh, rowptr, col, hBh);
    gemm_f16_s<true><<<gS, 256, SMEMS>>>(hBh, wgt + 1 * 4096, bg2, ndst, nsrc, hAh, M, 64, 64);

    gather_h<<<gatherBlocks, 256>>>(hAh, rowptr, col, hBh);
    gemm_f16_s<true><<<gS, 256, SMEMS>>>(hBh, wgt + 2 * 4096, bg3, ndst, nsrc, hAh, M, 64, 64);

    gather_h<<<gatherBlocks, 256>>>(hAh, rowptr, col, hBh);
    gemm_f16_s<false><<<gS, 256, SMEMS>>>(hBh, wgt + 3 * 4096, bg4, ndst, nullptr, out, M, 40, 64);
}